// round 7
// baseline (speedup 1.0000x reference)
#include <cuda_runtime.h>
#include <cuda_bf16.h>

#define NV 10000
#define BB 8
#define NE 2000000
#define NB (NV * BB)

#define HALF 5000                 // nodes [0, HALF) gathered from smem
#define SMF  (HALF * 8)           // floats staged in smem (160 KB)
#define PASS_BLK 1024             // threads per pass CTA
#define PASS_GRID 148             // one CTA per SM (smem-limited)

// Node tables in [N, B] layout: each node's 8 batch values = one 32B chunk.
__device__ float g_xt[NB];            // x transposed
__device__ float g_fx[NB];            // tanh(x)
__device__ float g_pred[NB];          // scatter accumulator (by tgt)
__device__ float g_err[NB];           // x - pred
__device__ float g_aggr[NB];          // scatter accumulator (by src)
__device__ unsigned int g_packed[NE]; // (src<<14)|tgt, written by pass1
__device__ int   g_idx64;             // 1 if edge_index is int64

// ---------------------------------------------------------------------------
// prep: transpose values -> [N,B], tanh, zero accumulators, sniff idx dtype.
__global__ __launch_bounds__(256) void prep_kernel(
        const float* __restrict__ values,
        const unsigned int* __restrict__ ei_words) {
    if (blockIdx.x == 0 && threadIdx.x == 0) {
        int is64 = 1;
        #pragma unroll
        for (int i = 0; i < 64; i++) {
            if (ei_words[2 * i + 1] != 0u) { is64 = 0; break; }
        }
        g_idx64 = is64;
    }
    int n = blockIdx.x * blockDim.x + threadIdx.x;
    if (n >= NV) return;
    float x[8], fx[8];
    #pragma unroll
    for (int b = 0; b < 8; b++) {
        x[b]  = values[b * NV + n];
        fx[b] = tanhf(x[b]);
    }
    float4* xt4 = reinterpret_cast<float4*>(g_xt)   + n * 2;
    float4* fx4 = reinterpret_cast<float4*>(g_fx)   + n * 2;
    float4* pr4 = reinterpret_cast<float4*>(g_pred) + n * 2;
    float4* ag4 = reinterpret_cast<float4*>(g_aggr) + n * 2;
    xt4[0] = make_float4(x[0], x[1], x[2], x[3]);
    xt4[1] = make_float4(x[4], x[5], x[6], x[7]);
    fx4[0] = make_float4(fx[0], fx[1], fx[2], fx[3]);
    fx4[1] = make_float4(fx[4], fx[5], fx[6], fx[7]);
    float4 z = make_float4(0.f, 0.f, 0.f, 0.f);
    pr4[0] = z; pr4[1] = z;
    ag4[0] = z; ag4[1] = z;
}

// ---------------------------------------------------------------------------
__device__ __forceinline__ void red_add_v4(float* p, float4 v) {
    asm volatile("red.global.add.v4.f32 [%0], {%1, %2, %3, %4};"
                 :: "l"(p), "f"(v.x), "f"(v.y), "f"(v.z), "f"(v.w));
}

// ===========================================================================
// Edge passes: 2 lanes/edge (pair p = lane&1 owns one 16B half of the node's
// 32B chunk). Gather-table nodes [0, HALF) are staged per-CTA in smem: those
// gathers are LDS (bypass the L1tex line-replay queue); nodes >= HALF gather
// via LDG. Scatter stays global red.v4.
// 148 CTAs x 1024 threads, contiguous edge chunks per CTA.
// ===========================================================================

__device__ __forceinline__ void stage_table(float* sdst, const float* gsrc,
                                            int tid, int nthr) {
    const float4* s4 = reinterpret_cast<const float4*>(gsrc);
    float4*       d4 = reinterpret_cast<float4*>(sdst);
    for (int i = tid; i < SMF / 4; i += nthr) d4[i] = __ldg(s4 + i);
    __syncthreads();
}

// pass1: pred[tgt] += w * fx[src]; also writes packed (src<<14)|tgt.
__global__ __launch_bounds__(PASS_BLK, 1) void pass1_kernel(
        const void* __restrict__ ei, const float* __restrict__ w) {
    extern __shared__ float sfx[];
    int tid  = threadIdx.x;
    stage_table(sfx, g_fx, tid, PASS_BLK);

    int lane = tid & 31;
    int wb   = tid >> 5;            // warp in block (0..31)
    int p    = lane & 1;            // 16B half selector
    int eo   = lane >> 1;           // edge slot in warp step (0..15)

    int chunk = (NE + PASS_GRID - 1) / PASS_GRID;
    int e0 = blockIdx.x * chunk;
    int e1 = e0 + chunk; if (e1 > NE) e1 = NE;

    const int idx64 = g_idx64;
    const float4* fx4g = reinterpret_cast<const float4*>(g_fx);
    const float4* sfx4 = reinterpret_cast<const float4*>(sfx);

    for (int es = e0 + wb * 16; es < e1; es += 32 * 16) {
        int e = es + eo;
        bool ok = (e < e1);
        int ec = ok ? e : e0;
        int s, t;
        if (idx64) {
            s = (int)__ldg((const long long*)ei + ec);
            t = (int)__ldg((const long long*)ei + NE + ec);
        } else {
            s = __ldg((const int*)ei + ec);
            t = __ldg((const int*)ei + NE + ec);
        }
        float we = __ldg(w + ec);
        float4 v;
        if (s < HALF) v = sfx4[s * 2 + p];
        else          v = __ldg(fx4g + s * 2 + p);
        if (ok) {
            if (p == 0)
                g_packed[e] = ((unsigned)s << 14) | (unsigned)t;
            red_add_v4(g_pred + (size_t)t * 8 + p * 4,
                       make_float4(we * v.x, we * v.y, we * v.z, we * v.w));
        }
    }
}

// ---------------------------------------------------------------------------
__global__ __launch_bounds__(256) void err_kernel() {
    int i = blockIdx.x * blockDim.x + threadIdx.x;   // float4 index
    if (i >= NB / 4) return;
    const float4* xt4 = reinterpret_cast<const float4*>(g_xt);
    const float4* pr4 = reinterpret_cast<const float4*>(g_pred);
    float4 x = xt4[i], p = pr4[i];
    reinterpret_cast<float4*>(g_err)[i] =
        make_float4(x.x - p.x, x.y - p.y, x.z - p.z, x.w - p.w);
}

// ---------------------------------------------------------------------------
// pass2: aggr[src] += w * err[tgt]  (packed indices; err[0:HALF) in smem)
__global__ __launch_bounds__(PASS_BLK, 1) void pass2_kernel(
        const float* __restrict__ w) {
    extern __shared__ float ser[];
    int tid  = threadIdx.x;
    stage_table(ser, g_err, tid, PASS_BLK);

    int lane = tid & 31;
    int wb   = tid >> 5;
    int p    = lane & 1;
    int eo   = lane >> 1;

    int chunk = (NE + PASS_GRID - 1) / PASS_GRID;
    int e0 = blockIdx.x * chunk;
    int e1 = e0 + chunk; if (e1 > NE) e1 = NE;

    const float4* er4g = reinterpret_cast<const float4*>(g_err);
    const float4* ser4 = reinterpret_cast<const float4*>(ser);

    for (int es = e0 + wb * 16; es < e1; es += 32 * 16) {
        int e = es + eo;
        bool ok = (e < e1);
        int ec = ok ? e : e0;
        unsigned pk = __ldg(g_packed + ec);
        int s = (int)(pk >> 14);
        int t = (int)(pk & 16383u);
        float we = __ldg(w + ec);
        float4 v;
        if (t < HALF) v = ser4[t * 2 + p];
        else          v = __ldg(er4g + t * 2 + p);
        if (ok) {
            red_add_v4(g_aggr + (size_t)s * 8 + p * 4,
                       make_float4(we * v.x, we * v.y, we * v.z, we * v.w));
        }
    }
}

// ---------------------------------------------------------------------------
// out layout: [3, B*N], inner [B, N] (row b, node n at b*N + n)
__global__ __launch_bounds__(256) void final_kernel(float* __restrict__ out) {
    int n = blockIdx.x * blockDim.x + threadIdx.x;
    if (n >= NV) return;
    const float4* fx4 = reinterpret_cast<const float4*>(g_fx)   + n * 2;
    const float4* pr4 = reinterpret_cast<const float4*>(g_pred) + n * 2;
    const float4* er4 = reinterpret_cast<const float4*>(g_err)  + n * 2;
    const float4* ag4 = reinterpret_cast<const float4*>(g_aggr) + n * 2;
    float fx[8], pr[8], er[8], ag[8];
    float4 t;
    t = fx4[0]; fx[0]=t.x; fx[1]=t.y; fx[2]=t.z; fx[3]=t.w;
    t = fx4[1]; fx[4]=t.x; fx[5]=t.y; fx[6]=t.z; fx[7]=t.w;
    t = pr4[0]; pr[0]=t.x; pr[1]=t.y; pr[2]=t.z; pr[3]=t.w;
    t = pr4[1]; pr[4]=t.x; pr[5]=t.y; pr[6]=t.z; pr[7]=t.w;
    t = er4[0]; er[0]=t.x; er[1]=t.y; er[2]=t.z; er[3]=t.w;
    t = er4[1]; er[4]=t.x; er[5]=t.y; er[6]=t.z; er[7]=t.w;
    t = ag4[0]; ag[0]=t.x; ag[1]=t.y; ag[2]=t.z; ag[3]=t.w;
    t = ag4[1]; ag[4]=t.x; ag[5]=t.y; ag[6]=t.z; ag[7]=t.w;
    #pragma unroll
    for (int b = 0; b < 8; b++) {
        float dx = er[b] - (1.0f - fx[b] * fx[b]) * ag[b];
        int o = b * NV + n;
        out[o]          = pr[b];
        out[NB + o]     = er[b];
        out[2 * NB + o] = dx;
    }
}

// ---------------------------------------------------------------------------
extern "C" void kernel_launch(void* const* d_in, const int* in_sizes, int n_in,
                              void* d_out, int out_size) {
    const float* values  = (const float*)d_in[0];
    const float* weights = (const float*)d_in[1];
    const void*  ei      = (const void*)d_in[2];
    float* out = (float*)d_out;

    const int SMEM_BYTES = SMF * (int)sizeof(float);   // 160 KB
    cudaFuncSetAttribute(pass1_kernel,
                         cudaFuncAttributeMaxDynamicSharedMemorySize, SMEM_BYTES);
    cudaFuncSetAttribute(pass2_kernel,
                         cudaFuncAttributeMaxDynamicSharedMemorySize, SMEM_BYTES);

    const int TB = 256;
    prep_kernel <<<(NV + TB - 1) / TB, TB>>>(values, (const unsigned int*)ei);
    pass1_kernel<<<PASS_GRID, PASS_BLK, SMEM_BYTES>>>(ei, weights);
    err_kernel  <<<(NB / 4 + TB - 1) / TB, TB>>>();
    pass2_kernel<<<PASS_GRID, PASS_BLK, SMEM_BYTES>>>(weights);
    final_kernel<<<(NV + TB - 1) / TB, TB>>>(out);
}

// round 8
// speedup vs baseline: 1.1063x; 1.1063x over previous
#include <cuda_runtime.h>
#include <cuda_bf16.h>

#define NV 10000
#define BB 8
#define NE 2000000
#define NB (NV * BB)

// Node tables in [N, B] layout: each node's 8 batch values = one 32B chunk.
__device__ float g_xt[NB];            // x transposed
__device__ float g_fx[NB];            // tanh(x)
__device__ float g_pred[NB];          // scatter accumulator (by tgt)
__device__ float g_err[NB];           // x - pred
__device__ float g_aggr[NB];          // scatter accumulator (by src)
__device__ unsigned int g_packed[NE]; // (src<<14)|tgt, written by pass1
__device__ int   g_idx64;             // 1 if edge_index is int64

// ---------------------------------------------------------------------------
// prep: transpose values -> [N,B], tanh, zero accumulators, sniff idx dtype.
__global__ __launch_bounds__(256) void prep_kernel(
        const float* __restrict__ values,
        const unsigned int* __restrict__ ei_words) {
    if (blockIdx.x == 0 && threadIdx.x == 0) {
        int is64 = 1;
        #pragma unroll
        for (int i = 0; i < 64; i++) {
            if (ei_words[2 * i + 1] != 0u) { is64 = 0; break; }
        }
        g_idx64 = is64;
    }
    int n = blockIdx.x * blockDim.x + threadIdx.x;
    if (n >= NV) return;
    float x[8], fx[8];
    #pragma unroll
    for (int b = 0; b < 8; b++) {
        x[b]  = values[b * NV + n];
        fx[b] = tanhf(x[b]);
    }
    float4* xt4 = reinterpret_cast<float4*>(g_xt)   + n * 2;
    float4* fx4 = reinterpret_cast<float4*>(g_fx)   + n * 2;
    float4* pr4 = reinterpret_cast<float4*>(g_pred) + n * 2;
    float4* ag4 = reinterpret_cast<float4*>(g_aggr) + n * 2;
    xt4[0] = make_float4(x[0], x[1], x[2], x[3]);
    xt4[1] = make_float4(x[4], x[5], x[6], x[7]);
    fx4[0] = make_float4(fx[0], fx[1], fx[2], fx[3]);
    fx4[1] = make_float4(fx[4], fx[5], fx[6], fx[7]);
    float4 z = make_float4(0.f, 0.f, 0.f, 0.f);
    pr4[0] = z; pr4[1] = z;
    ag4[0] = z; ag4[1] = z;
}

// ---------------------------------------------------------------------------
__device__ __forceinline__ void red_add_v4(float* p, float4 v) {
    asm volatile("red.global.add.v4.f32 [%0], {%1, %2, %3, %4};"
                 :: "l"(p), "f"(v.x), "f"(v.y), "f"(v.z), "f"(v.w));
}

// ===========================================================================
// Edge passes (persistent grid): 2 lanes per edge, zero shuffles.
// Lane pair (2k, 2k+1) owns one edge; parity p = lane&1 selects which 16B
// half of the node's 32B batch-chunk this lane handles. One LDG.128 gathers
// (adjacent lanes -> same 32B chunk -> 1 line/edge); one full-warp red.v4
// scatters; no shfl, no predication.
//
// Work unit = "step" of 64 edges per warp (4 unrolled sub-steps of 16).
// NE = 2,000,000 = 31250 steps exactly -> NO bounds checks anywhere.
// Fixed grid of PGRID CTAs; each warp grid-strides over steps.
// ===========================================================================

#define EPT 4                     // sub-steps per step (16 edges each)
#define PCTAS 6                   // resident CTAs per SM
#define PGRID (148 * PCTAS)       // persistent grid
#define NWARPS (PGRID * 8)        // total warps (256-thread CTAs)
#define NSTEPS (NE / 64)          // 31250

// pass1: pred[tgt] += w * fx[src]; also writes packed (src<<14)|tgt.
__global__ __launch_bounds__(256) void pass1_kernel(
        const void* __restrict__ ei, const float* __restrict__ w) {
    int lane = threadIdx.x & 31;
    int p    = lane & 1;        // 16B half selector
    int eo   = lane >> 1;       // edge slot within sub-step (0..15)
    int W    = blockIdx.x * 8 + (threadIdx.x >> 5);
    const int idx64 = g_idx64;
    const float4* fx4g = reinterpret_cast<const float4*>(g_fx);

    for (int step = W; step < NSTEPS; step += NWARPS) {
        int base = step * 64 + eo;
        int   s[EPT], t[EPT];
        float we[EPT];
        float4 v[EPT];

        #pragma unroll
        for (int k = 0; k < EPT; k++) {
            int e = base + k * 16;
            if (idx64) {
                s[k] = (int)__ldg((const long long*)ei + e);
                t[k] = (int)__ldg((const long long*)ei + NE + e);
            } else {
                s[k] = __ldg((const int*)ei + e);
                t[k] = __ldg((const int*)ei + NE + e);
            }
            we[k] = __ldg(w + e);
        }
        #pragma unroll
        for (int k = 0; k < EPT; k++) {
            v[k] = __ldg(fx4g + s[k] * 2 + p);
        }
        #pragma unroll
        for (int k = 0; k < EPT; k++) {
            int e = base + k * 16;
            if (p == 0)
                g_packed[e] = ((unsigned)s[k] << 14) | (unsigned)t[k];
            float wk = we[k];
            red_add_v4(g_pred + (size_t)t[k] * 8 + p * 4,
                       make_float4(wk * v[k].x, wk * v[k].y,
                                   wk * v[k].z, wk * v[k].w));
        }
    }
}

// ---------------------------------------------------------------------------
__global__ __launch_bounds__(256) void err_kernel() {
    int i = blockIdx.x * blockDim.x + threadIdx.x;   // float4 index
    if (i >= NB / 4) return;
    const float4* xt4 = reinterpret_cast<const float4*>(g_xt);
    const float4* pr4 = reinterpret_cast<const float4*>(g_pred);
    float4 x = xt4[i], p = pr4[i];
    reinterpret_cast<float4*>(g_err)[i] =
        make_float4(x.x - p.x, x.y - p.y, x.z - p.z, x.w - p.w);
}

// ---------------------------------------------------------------------------
// pass2: aggr[src] += w * err[tgt]  (2 lanes/edge, packed indices)
__global__ __launch_bounds__(256) void pass2_kernel(const float* __restrict__ w) {
    int lane = threadIdx.x & 31;
    int p    = lane & 1;
    int eo   = lane >> 1;
    int W    = blockIdx.x * 8 + (threadIdx.x >> 5);
    const float4* er4g = reinterpret_cast<const float4*>(g_err);

    for (int step = W; step < NSTEPS; step += NWARPS) {
        int base = step * 64 + eo;
        int   s[EPT], t[EPT];
        float we[EPT];
        float4 v[EPT];

        #pragma unroll
        for (int k = 0; k < EPT; k++) {
            int e = base + k * 16;
            unsigned pk = __ldg(g_packed + e);
            s[k] = (int)(pk >> 14);
            t[k] = (int)(pk & 16383u);
            we[k] = __ldg(w + e);
        }
        #pragma unroll
        for (int k = 0; k < EPT; k++) {
            v[k] = __ldg(er4g + t[k] * 2 + p);
        }
        #pragma unroll
        for (int k = 0; k < EPT; k++) {
            float wk = we[k];
            red_add_v4(g_aggr + (size_t)s[k] * 8 + p * 4,
                       make_float4(wk * v[k].x, wk * v[k].y,
                                   wk * v[k].z, wk * v[k].w));
        }
    }
}

// ---------------------------------------------------------------------------
// out layout: [3, B*N], inner [B, N] (row b, node n at b*N + n)
__global__ __launch_bounds__(256) void final_kernel(float* __restrict__ out) {
    int n = blockIdx.x * blockDim.x + threadIdx.x;
    if (n >= NV) return;
    const float4* fx4 = reinterpret_cast<const float4*>(g_fx)   + n * 2;
    const float4* pr4 = reinterpret_cast<const float4*>(g_pred) + n * 2;
    const float4* er4 = reinterpret_cast<const float4*>(g_err)  + n * 2;
    const float4* ag4 = reinterpret_cast<const float4*>(g_aggr) + n * 2;
    float fx[8], pr[8], er[8], ag[8];
    float4 t;
    t = fx4[0]; fx[0]=t.x; fx[1]=t.y; fx[2]=t.z; fx[3]=t.w;
    t = fx4[1]; fx[4]=t.x; fx[5]=t.y; fx[6]=t.z; fx[7]=t.w;
    t = pr4[0]; pr[0]=t.x; pr[1]=t.y; pr[2]=t.z; pr[3]=t.w;
    t = pr4[1]; pr[4]=t.x; pr[5]=t.y; pr[6]=t.z; pr[7]=t.w;
    t = er4[0]; er[0]=t.x; er[1]=t.y; er[2]=t.z; er[3]=t.w;
    t = er4[1]; er[4]=t.x; er[5]=t.y; er[6]=t.z; er[7]=t.w;
    t = ag4[0]; ag[0]=t.x; ag[1]=t.y; ag[2]=t.z; ag[3]=t.w;
    t = ag4[1]; ag[4]=t.x; ag[5]=t.y; ag[6]=t.z; ag[7]=t.w;
    #pragma unroll
    for (int b = 0; b < 8; b++) {
        float dx = er[b] - (1.0f - fx[b] * fx[b]) * ag[b];
        int o = b * NV + n;
        out[o]          = pr[b];
        out[NB + o]     = er[b];
        out[2 * NB + o] = dx;
    }
}

// ---------------------------------------------------------------------------
extern "C" void kernel_launch(void* const* d_in, const int* in_sizes, int n_in,
                              void* d_out, int out_size) {
    const float* values  = (const float*)d_in[0];
    const float* weights = (const float*)d_in[1];
    const void*  ei      = (const void*)d_in[2];
    float* out = (float*)d_out;

    const int TB = 256;
    prep_kernel <<<(NV + TB - 1) / TB, TB>>>(values, (const unsigned int*)ei);
    pass1_kernel<<<PGRID, TB>>>(ei, weights);
    err_kernel  <<<(NB / 4 + TB - 1) / TB, TB>>>();
    pass2_kernel<<<PGRID, TB>>>(weights);
    final_kernel<<<(NV + TB - 1) / TB, TB>>>(out);
}

// round 9
// speedup vs baseline: 1.1978x; 1.0827x over previous
#include <cuda_runtime.h>
#include <cuda_bf16.h>

#define NV 10000
#define BB 8
#define NE 2000000
#define NB (NV * BB)

// Node tables in [N, B] layout: each node's 8 batch values = one 32B chunk.
__device__ float g_xt[NB];        // x transposed
__device__ float g_fx[NB];        // tanh(x)
__device__ float g_err[NB];       // init x; pass1 reds -w*fx -> becomes x-pred
__device__ float g_aggr[NB];      // scatter accumulator (by src)
__device__ uint2 g_epay[NE];      // {w_bits, (src<<14)|tgt} written by pass1
__device__ int   g_idx64;         // 1 if edge_index is int64

// ---------------------------------------------------------------------------
// prep: transpose values -> [N,B], tanh, err := x, aggr := 0, sniff idx dtype.
__global__ __launch_bounds__(256) void prep_kernel(
        const float* __restrict__ values,
        const unsigned int* __restrict__ ei_words) {
    if (blockIdx.x == 0 && threadIdx.x == 0) {
        int is64 = 1;
        #pragma unroll
        for (int i = 0; i < 64; i++) {
            if (ei_words[2 * i + 1] != 0u) { is64 = 0; break; }
        }
        g_idx64 = is64;
    }
    int n = blockIdx.x * blockDim.x + threadIdx.x;
    if (n >= NV) return;
    float x[8], fx[8];
    #pragma unroll
    for (int b = 0; b < 8; b++) {
        x[b]  = values[b * NV + n];
        fx[b] = tanhf(x[b]);
    }
    float4* xt4 = reinterpret_cast<float4*>(g_xt)   + n * 2;
    float4* fx4 = reinterpret_cast<float4*>(g_fx)   + n * 2;
    float4* er4 = reinterpret_cast<float4*>(g_err)  + n * 2;
    float4* ag4 = reinterpret_cast<float4*>(g_aggr) + n * 2;
    float4 x0 = make_float4(x[0], x[1], x[2], x[3]);
    float4 x1 = make_float4(x[4], x[5], x[6], x[7]);
    xt4[0] = x0;  xt4[1] = x1;
    er4[0] = x0;  er4[1] = x1;     // err starts at x; pass1 subtracts pred
    fx4[0] = make_float4(fx[0], fx[1], fx[2], fx[3]);
    fx4[1] = make_float4(fx[4], fx[5], fx[6], fx[7]);
    float4 z = make_float4(0.f, 0.f, 0.f, 0.f);
    ag4[0] = z; ag4[1] = z;
}

// ---------------------------------------------------------------------------
__device__ __forceinline__ void red_add_v4(float* p, float4 v) {
    asm volatile("red.global.add.v4.f32 [%0], {%1, %2, %3, %4};"
                 :: "l"(p), "f"(v.x), "f"(v.y), "f"(v.z), "f"(v.w));
}

// ===========================================================================
// Edge passes: 2 lanes per edge, zero shuffles (R6 geometry).
// Lane pair (2k, 2k+1) owns one edge; parity p = lane&1 selects which 16B
// half of the node's 32B batch-chunk this lane handles. One LDG.128 gathers
// (adjacent lanes -> same 32B chunk -> 1 line/edge); one full-warp red.v4
// scatters. Each warp processes 16*EPT contiguous edges, all loads batched.
// ===========================================================================

#define EPT 4   // warp-steps per thread (16 edges per warp-step)

// pass1: err[tgt] -= w * fx[src]  (pred folded into err via negated red);
// also writes payload {w, (src<<14)|tgt} for pass2.
__global__ __launch_bounds__(256) void pass1_kernel(
        const void* __restrict__ ei, const float* __restrict__ w) {
    int tid  = blockIdx.x * blockDim.x + threadIdx.x;
    int warp = tid >> 5;
    int lane = tid & 31;
    int p    = lane & 1;        // 16B half selector
    int eo   = lane >> 1;       // edge slot within warp-step (0..15)
    int base = warp * (16 * EPT) + eo;

    int   s[EPT], t[EPT];
    float we[EPT];
    float4 v[EPT];
    const int idx64 = g_idx64;

    #pragma unroll
    for (int k = 0; k < EPT; k++) {
        int e  = base + k * 16;
        int ec = (e < NE) ? e : 0;
        if (idx64) {
            s[k] = (int)__ldg((const long long*)ei + ec);
            t[k] = (int)__ldg((const long long*)ei + NE + ec);
        } else {
            s[k] = __ldg((const int*)ei + ec);
            t[k] = __ldg((const int*)ei + NE + ec);
        }
        we[k] = __ldg(w + ec);
    }
    #pragma unroll
    for (int k = 0; k < EPT; k++) {
        v[k] = __ldg(reinterpret_cast<const float4*>(g_fx) + s[k] * 2 + p);
    }
    #pragma unroll
    for (int k = 0; k < EPT; k++) {
        int e = base + k * 16;
        if (e < NE) {
            if (p == 0)
                g_epay[e] = make_uint2(__float_as_uint(we[k]),
                                       ((unsigned)s[k] << 14) | (unsigned)t[k]);
            float wk = -we[k];                 // negated: err accumulates x - pred
            red_add_v4(g_err + (size_t)t[k] * 8 + p * 4,
                       make_float4(wk * v[k].x, wk * v[k].y,
                                   wk * v[k].z, wk * v[k].w));
        }
    }
}

// ---------------------------------------------------------------------------
// pass2: aggr[src] += w * err[tgt]  (2 lanes/edge, single 8B payload load)
__global__ __launch_bounds__(256) void pass2_kernel() {
    int tid  = blockIdx.x * blockDim.x + threadIdx.x;
    int warp = tid >> 5;
    int lane = tid & 31;
    int p    = lane & 1;
    int eo   = lane >> 1;
    int base = warp * (16 * EPT) + eo;

    int   s[EPT], t[EPT];
    float we[EPT];
    float4 v[EPT];

    #pragma unroll
    for (int k = 0; k < EPT; k++) {
        int e  = base + k * 16;
        int ec = (e < NE) ? e : 0;
        uint2 pay = __ldg(g_epay + ec);
        we[k] = __uint_as_float(pay.x);
        s[k]  = (int)(pay.y >> 14);
        t[k]  = (int)(pay.y & 16383u);
    }
    #pragma unroll
    for (int k = 0; k < EPT; k++) {
        v[k] = __ldg(reinterpret_cast<const float4*>(g_err) + t[k] * 2 + p);
    }
    #pragma unroll
    for (int k = 0; k < EPT; k++) {
        int e = base + k * 16;
        if (e < NE) {
            float wk = we[k];
            red_add_v4(g_aggr + (size_t)s[k] * 8 + p * 4,
                       make_float4(wk * v[k].x, wk * v[k].y,
                                   wk * v[k].z, wk * v[k].w));
        }
    }
}

// ---------------------------------------------------------------------------
// out layout: [3, B*N], inner [B, N]. pred reconstructed as x - err.
__global__ __launch_bounds__(256) void final_kernel(float* __restrict__ out) {
    int n = blockIdx.x * blockDim.x + threadIdx.x;
    if (n >= NV) return;
    const float4* xt4 = reinterpret_cast<const float4*>(g_xt)   + n * 2;
    const float4* fx4 = reinterpret_cast<const float4*>(g_fx)   + n * 2;
    const float4* er4 = reinterpret_cast<const float4*>(g_err)  + n * 2;
    const float4* ag4 = reinterpret_cast<const float4*>(g_aggr) + n * 2;
    float x[8], fx[8], er[8], ag[8];
    float4 t;
    t = xt4[0]; x[0]=t.x; x[1]=t.y; x[2]=t.z; x[3]=t.w;
    t = xt4[1]; x[4]=t.x; x[5]=t.y; x[6]=t.z; x[7]=t.w;
    t = fx4[0]; fx[0]=t.x; fx[1]=t.y; fx[2]=t.z; fx[3]=t.w;
    t = fx4[1]; fx[4]=t.x; fx[5]=t.y; fx[6]=t.z; fx[7]=t.w;
    t = er4[0]; er[0]=t.x; er[1]=t.y; er[2]=t.z; er[3]=t.w;
    t = er4[1]; er[4]=t.x; er[5]=t.y; er[6]=t.z; er[7]=t.w;
    t = ag4[0]; ag[0]=t.x; ag[1]=t.y; ag[2]=t.z; ag[3]=t.w;
    t = ag4[1]; ag[4]=t.x; ag[5]=t.y; ag[6]=t.z; ag[7]=t.w;
    #pragma unroll
    for (int b = 0; b < 8; b++) {
        float pred = x[b] - er[b];
        float dx   = er[b] - (1.0f - fx[b] * fx[b]) * ag[b];
        int o = b * NV + n;
        out[o]          = pred;
        out[NB + o]     = er[b];
        out[2 * NB + o] = dx;
    }
}

// ---------------------------------------------------------------------------
extern "C" void kernel_launch(void* const* d_in, const int* in_sizes, int n_in,
                              void* d_out, int out_size) {
    const float* values  = (const float*)d_in[0];
    const float* weights = (const float*)d_in[1];
    const void*  ei      = (const void*)d_in[2];
    float* out = (float*)d_out;

    const int TB = 256;
    // edge kernels: 1 warp per 16*EPT edges (R6 geometry)
    int nwarps  = (NE + 16 * EPT - 1) / (16 * EPT);   // 31250
    int nblocks = (nwarps * 32 + TB - 1) / TB;        // 3907

    prep_kernel <<<(NV + TB - 1) / TB, TB>>>(values, (const unsigned int*)ei);
    pass1_kernel<<<nblocks, TB>>>(ei, weights);
    pass2_kernel<<<nblocks, TB>>>();
    final_kernel<<<(NV + TB - 1) / TB, TB>>>(out);
}

// round 11
// speedup vs baseline: 1.2041x; 1.0052x over previous
#include <cuda_runtime.h>
#include <cuda_bf16.h>

#define NV 10000
#define BB 8
#define NE 2000000
#define NB (NV * BB)

// Node tables in [N, B] layout: each node's 8 batch values = one 32B chunk.
__device__ float g_xt[NB];        // x transposed
__device__ float g_fx[NB];        // tanh(x)
__device__ float g_err[NB];       // init x; pass1 reds -w*fx -> becomes x-pred
__device__ float g_aggr[NB];      // scatter accumulator (by src)
__device__ uint2 g_epay[NE];      // {w_bits, (src<<14)|tgt} written by pass1
__device__ int   g_idx64;         // 1 if edge_index is int64

// ---------------------------------------------------------------------------
// prep: one thread per (node, batch) element. Coalesced 4B writes to all
// four tables (linear idx i = n*8+b IS the [N,B] address), one tanh/thread.
__global__ __launch_bounds__(256) void prep_kernel(
        const float* __restrict__ values,
        const unsigned int* __restrict__ ei_words) {
    int i = blockIdx.x * blockDim.x + threadIdx.x;
    if (i == 0) {   // sniff edge_index dtype (indices < 10000 -> odd words 0)
        int is64 = 1;
        #pragma unroll
        for (int k = 0; k < 64; k++) {
            if (ei_words[2 * k + 1] != 0u) { is64 = 0; break; }
        }
        g_idx64 = is64;
    }
    if (i >= NB) return;
    int n = i >> 3;
    int b = i & 7;
    float x  = __ldg(values + b * NV + n);
    float fx = tanhf(x);
    g_xt[i]   = x;
    g_fx[i]   = fx;
    g_err[i]  = x;      // err starts at x; pass1 subtracts pred via red
    g_aggr[i] = 0.0f;
}

// ---------------------------------------------------------------------------
__device__ __forceinline__ void red_add_v4(float* p, float4 v) {
    asm volatile("red.global.add.v4.f32 [%0], {%1, %2, %3, %4};"
                 :: "l"(p), "f"(v.x), "f"(v.y), "f"(v.z), "f"(v.w));
}

// ===========================================================================
// Edge passes: 2 lanes per edge, zero shuffles (confirmed at line floor).
// Lane pair (2k, 2k+1) owns one edge; parity p = lane&1 selects which 16B
// half of the node's 32B batch-chunk this lane handles. One LDG.128 gathers
// (adjacent lanes -> same 32B chunk -> 1 line/edge); one full-warp red.v4
// scatters. Each warp processes 16*EPT contiguous edges, all loads batched.
// ===========================================================================

#define EPT 4   // warp-steps per thread (16 edges per warp-step)

// pass1: err[tgt] -= w * fx[src]  (pred folded into err via negated red);
// also writes payload {w, (src<<14)|tgt} for pass2.
__global__ __launch_bounds__(256) void pass1_kernel(
        const void* __restrict__ ei, const float* __restrict__ w) {
    int tid  = blockIdx.x * blockDim.x + threadIdx.x;
    int warp = tid >> 5;
    int lane = tid & 31;
    int p    = lane & 1;        // 16B half selector
    int eo   = lane >> 1;       // edge slot within warp-step (0..15)
    int base = warp * (16 * EPT) + eo;

    int   s[EPT], t[EPT];
    float we[EPT];
    float4 v[EPT];
    const int idx64 = g_idx64;

    #pragma unroll
    for (int k = 0; k < EPT; k++) {
        int e  = base + k * 16;
        int ec = (e < NE) ? e : 0;
        if (idx64) {
            s[k] = (int)__ldg((const long long*)ei + ec);
            t[k] = (int)__ldg((const long long*)ei + NE + ec);
        } else {
            s[k] = __ldg((const int*)ei + ec);
            t[k] = __ldg((const int*)ei + NE + ec);
        }
        we[k] = __ldg(w + ec);
    }
    #pragma unroll
    for (int k = 0; k < EPT; k++) {
        v[k] = __ldg(reinterpret_cast<const float4*>(g_fx) + s[k] * 2 + p);
    }
    #pragma unroll
    for (int k = 0; k < EPT; k++) {
        int e = base + k * 16;
        if (e < NE) {
            if (p == 0)
                g_epay[e] = make_uint2(__float_as_uint(we[k]),
                                       ((unsigned)s[k] << 14) | (unsigned)t[k]);
            float wk = -we[k];                 // negated: err accumulates x - pred
            red_add_v4(g_err + (size_t)t[k] * 8 + p * 4,
                       make_float4(wk * v[k].x, wk * v[k].y,
                                   wk * v[k].z, wk * v[k].w));
        }
    }
}

// ---------------------------------------------------------------------------
// pass2: aggr[src] += w * err[tgt]  (2 lanes/edge, single 8B payload load)
__global__ __launch_bounds__(256) void pass2_kernel() {
    int tid  = blockIdx.x * blockDim.x + threadIdx.x;
    int warp = tid >> 5;
    int lane = tid & 31;
    int p    = lane & 1;
    int eo   = lane >> 1;
    int base = warp * (16 * EPT) + eo;

    int   s[EPT], t[EPT];
    float we[EPT];
    float4 v[EPT];

    #pragma unroll
    for (int k = 0; k < EPT; k++) {
        int e  = base + k * 16;
        int ec = (e < NE) ? e : 0;
        uint2 pay = __ldg(g_epay + ec);
        we[k] = __uint_as_float(pay.x);
        s[k]  = (int)(pay.y >> 14);
        t[k]  = (int)(pay.y & 16383u);
    }
    #pragma unroll
    for (int k = 0; k < EPT; k++) {
        v[k] = __ldg(reinterpret_cast<const float4*>(g_err) + t[k] * 2 + p);
    }
    #pragma unroll
    for (int k = 0; k < EPT; k++) {
        int e = base + k * 16;
        if (e < NE) {
            float wk = we[k];
            red_add_v4(g_aggr + (size_t)s[k] * 8 + p * 4,
                       make_float4(wk * v[k].x, wk * v[k].y,
                                   wk * v[k].z, wk * v[k].w));
        }
    }
}

// ---------------------------------------------------------------------------
// final: one thread per (node, batch) element. Coalesced 4B reads from the
// tables (i = n*8+b); pred reconstructed as x - err.
// out layout: [3, B*N], inner [B, N].
__global__ __launch_bounds__(256) void final_kernel(float* __restrict__ out) {
    int i = blockIdx.x * blockDim.x + threadIdx.x;
    if (i >= NB) return;
    int n = i >> 3;
    int b = i & 7;
    float x  = g_xt[i];
    float fx = g_fx[i];
    float er = g_err[i];
    float ag = g_aggr[i];
    float pred = x - er;
    float dx   = er - (1.0f - fx * fx) * ag;
    int o = b * NV + n;
    out[o]          = pred;
    out[NB + o]     = er;
    out[2 * NB + o] = dx;
}

// ---------------------------------------------------------------------------
extern "C" void kernel_launch(void* const* d_in, const int* in_sizes, int n_in,
                              void* d_out, int out_size) {
    const float* values  = (const float*)d_in[0];
    const float* weights = (const float*)d_in[1];
    const void*  ei      = (const void*)d_in[2];
    float* out = (float*)d_out;

    const int TB = 256;
    // edge kernels: 1 warp per 16*EPT edges
    int nwarps  = (NE + 16 * EPT - 1) / (16 * EPT);   // 31250
    int nblocks = (nwarps * 32 + TB - 1) / TB;        // 3907

    prep_kernel <<<(NB + TB - 1) / TB, TB>>>(values, (const unsigned int*)ei);
    pass1_kernel<<<nblocks, TB>>>(ei, weights);
    pass2_kernel<<<nblocks, TB>>>();
    final_kernel<<<(NB + TB - 1) / TB, TB>>>(out);
}

// round 12
// speedup vs baseline: 1.2327x; 1.0238x over previous
#include <cuda_runtime.h>
#include <cuda_bf16.h>

#define NV 10000
#define BB 8
#define NE 2000000
#define NB (NV * BB)

// Edge-pass geometry: 64 edges per warp, 31250 warps exactly -> no bounds checks.
#define TBP 320                       // threads per pass CTA (10 warps)
#define NBLK (NE / 64 / (TBP / 32))   // 3125 CTAs

// Node tables in [N, B] layout: each node's 8 batch values = one 32B chunk.
__device__ float g_xt[NB];        // x transposed
__device__ float g_fx[NB];        // tanh(x)
__device__ float g_err[NB];       // init x; pass1 reds -w*fx -> becomes x-pred
__device__ float g_aggr[NB];      // scatter accumulator (by src)
__device__ uint2 g_epay[NE];      // {w_bits, (src<<14)|tgt} written by pass1

// ---------------------------------------------------------------------------
// prep: one thread per (node, batch) element; coalesced 4B table writes.
// Triggers early so pass1 (PDL) can start its independent prologue.
__global__ __launch_bounds__(256) void prep_kernel(
        const float* __restrict__ values) {
    cudaTriggerProgrammaticLaunchCompletion();
    int i = blockIdx.x * blockDim.x + threadIdx.x;
    if (i >= NB) return;
    int n = i >> 3;
    int b = i & 7;
    float x  = __ldg(values + b * NV + n);
    float fx = tanhf(x);
    g_xt[i]   = x;
    g_fx[i]   = fx;
    g_err[i]  = x;      // err starts at x; pass1 subtracts pred via red
    g_aggr[i] = 0.0f;
}

// ---------------------------------------------------------------------------
__device__ __forceinline__ void red_add_v4(float* p, float4 v) {
    asm volatile("red.global.add.v4.f32 [%0], {%1, %2, %3, %4};"
                 :: "l"(p), "f"(v.x), "f"(v.y), "f"(v.z), "f"(v.w));
}

// ===========================================================================
// Edge passes: 2 lanes per edge (confirmed at the L1tex line floor).
// Lane pair (2k, 2k+1) owns one edge; parity p = lane&1 selects which 16B
// half of the node's 32B batch-chunk this lane handles. One LDG.128 gathers
// (adjacent lanes -> same 32B chunk -> 1 line/edge); one full-warp red.v4
// scatters. Each warp covers 64 contiguous edges; loads batched first.
// PDL: pass1's idx/weight prologue + payload store are independent of prep
// and overlap it; the gather/red epilogue runs after GridDependencySync.
// ===========================================================================

// pass1: err[tgt] -= w * fx[src]; writes payload {w, (src<<14)|tgt}.
__global__ __launch_bounds__(TBP) void pass1_kernel(
        const void* __restrict__ ei, const float* __restrict__ w) {
    cudaTriggerProgrammaticLaunchCompletion();
    int lane = threadIdx.x & 31;
    int p    = lane & 1;        // 16B half selector
    int eo   = lane >> 1;       // edge slot within warp-step (0..15)
    int warp = blockIdx.x * (TBP / 32) + (threadIdx.x >> 5);
    int base = warp * 64 + eo;

    // self-sniff idx dtype (independent of prep): indices < 10000, so int64
    // means odd 32-bit words are all 0. P(false positive for int32) ~ 1e-16.
    const unsigned int* eiw = (const unsigned int*)ei;
    int idx64 = (eiw[1] == 0u) & (eiw[3] == 0u) & (eiw[5] == 0u) & (eiw[7] == 0u);

    int   s[4], t[4];
    float we[4];
    float4 v[4];

    #pragma unroll
    for (int k = 0; k < 4; k++) {
        int e = base + k * 16;
        if (idx64) {
            s[k] = (int)__ldg((const long long*)ei + e);
            t[k] = (int)__ldg((const long long*)ei + NE + e);
        } else {
            s[k] = __ldg((const int*)ei + e);
            t[k] = __ldg((const int*)ei + NE + e);
        }
        we[k] = __ldg(w + e);
    }
    #pragma unroll
    for (int k = 0; k < 4; k++) {
        int e = base + k * 16;
        if (p == 0)
            g_epay[e] = make_uint2(__float_as_uint(we[k]),
                                   ((unsigned)s[k] << 14) | (unsigned)t[k]);
    }

    cudaGridDependencySynchronize();   // wait for prep's fx/err tables

    #pragma unroll
    for (int k = 0; k < 4; k++) {
        v[k] = __ldg(reinterpret_cast<const float4*>(g_fx) + s[k] * 2 + p);
    }
    #pragma unroll
    for (int k = 0; k < 4; k++) {
        float wk = -we[k];             // negated: err accumulates x - pred
        red_add_v4(g_err + (size_t)t[k] * 8 + p * 4,
                   make_float4(wk * v[k].x, wk * v[k].y,
                               wk * v[k].z, wk * v[k].w));
    }
}

// ---------------------------------------------------------------------------
// pass2: aggr[src] += w * err[tgt]  (payload fully produced by pass1)
__global__ __launch_bounds__(TBP) void pass2_kernel() {
    cudaTriggerProgrammaticLaunchCompletion();
    cudaGridDependencySynchronize();   // wait for pass1 (payload + err)
    int lane = threadIdx.x & 31;
    int p    = lane & 1;
    int eo   = lane >> 1;
    int warp = blockIdx.x * (TBP / 32) + (threadIdx.x >> 5);
    int base = warp * 64 + eo;

    int   s[4], t[4];
    float we[4];
    float4 v[4];

    #pragma unroll
    for (int k = 0; k < 4; k++) {
        uint2 pay = __ldg(g_epay + base + k * 16);
        we[k] = __uint_as_float(pay.x);
        s[k]  = (int)(pay.y >> 14);
        t[k]  = (int)(pay.y & 16383u);
    }
    #pragma unroll
    for (int k = 0; k < 4; k++) {
        v[k] = __ldg(reinterpret_cast<const float4*>(g_err) + t[k] * 2 + p);
    }
    #pragma unroll
    for (int k = 0; k < 4; k++) {
        float wk = we[k];
        red_add_v4(g_aggr + (size_t)s[k] * 8 + p * 4,
                   make_float4(wk * v[k].x, wk * v[k].y,
                               wk * v[k].z, wk * v[k].w));
    }
}

// ---------------------------------------------------------------------------
// final: one thread per (node, batch) element; pred reconstructed as x - err.
// out layout: [3, B*N], inner [B, N].
__global__ __launch_bounds__(256) void final_kernel(float* __restrict__ out) {
    cudaGridDependencySynchronize();   // wait for pass2 (aggr)
    int i = blockIdx.x * blockDim.x + threadIdx.x;
    if (i >= NB) return;
    int n = i >> 3;
    int b = i & 7;
    float x  = g_xt[i];
    float fx = g_fx[i];
    float er = g_err[i];
    float ag = g_aggr[i];
    float pred = x - er;
    float dx   = er - (1.0f - fx * fx) * ag;
    int o = b * NV + n;
    out[o]          = pred;
    out[NB + o]     = er;
    out[2 * NB + o] = dx;
}

// ---------------------------------------------------------------------------
extern "C" void kernel_launch(void* const* d_in, const int* in_sizes, int n_in,
                              void* d_out, int out_size) {
    const float* values  = (const float*)d_in[0];
    const float* weights = (const float*)d_in[1];
    const void*  ei      = (const void*)d_in[2];
    float* out = (float*)d_out;

    prep_kernel<<<(NB + 255) / 256, 256>>>(values);

    cudaLaunchAttribute attr;
    attr.id = cudaLaunchAttributeProgrammaticStreamSerialization;
    attr.val.programmaticStreamSerializationAllowed = 1;

    cudaLaunchConfig_t cfg = {};
    cfg.attrs = &attr;
    cfg.numAttrs = 1;
    cfg.stream = 0;

    cfg.gridDim = dim3(NBLK);
    cfg.blockDim = dim3(TBP);
    cudaLaunchKernelEx(&cfg, pass1_kernel, (const void*)ei, weights);
    cudaLaunchKernelEx(&cfg, pass2_kernel);

    cfg.gridDim = dim3((NB + 255) / 256);
    cfg.blockDim = dim3(256);
    cudaLaunchKernelEx(&cfg, final_kernel, out);
}

// round 13
// speedup vs baseline: 1.2431x; 1.0084x over previous
#include <cuda_runtime.h>
#include <cuda_bf16.h>

#define NV 10000
#define BB 8
#define NE 2000000
#define NB (NV * BB)

// Edge-pass geometry: 64 edges per warp, 31250 warps exactly -> no bounds checks.
#define TBP 320                       // threads per pass CTA (10 warps)
#define NBLK (NE / 64 / (TBP / 32))   // 3125 CTAs

// Node tables in [N, B] layout: each node's 8 batch values = one 32B chunk.
__device__ float g_fx[NB];        // tanh(x)
__device__ float g_err[NB];       // init x; pass1 reds -w*fx -> becomes x-pred
__device__ float g_aggr[NB];      // scatter accumulator (by src)
__device__ uint2 g_epay[NE];      // {w_bits, (src<<14)|tgt} written by pass1

// ---------------------------------------------------------------------------
// prep: one thread per (node, batch) element; coalesced 4B table writes.
// Triggers at entry so pass1 (PDL) can start its independent prologue.
__global__ __launch_bounds__(256) void prep_kernel(
        const float* __restrict__ values) {
    cudaTriggerProgrammaticLaunchCompletion();
    int i = blockIdx.x * blockDim.x + threadIdx.x;
    if (i >= NB) return;
    int n = i >> 3;
    int b = i & 7;
    float x  = __ldg(values + b * NV + n);
    g_fx[i]   = tanhf(x);
    g_err[i]  = x;      // err starts at x; pass1 subtracts pred via red
    g_aggr[i] = 0.0f;
}

// ---------------------------------------------------------------------------
__device__ __forceinline__ void red_add_v4(float* p, float4 v) {
    asm volatile("red.global.add.v4.f32 [%0], {%1, %2, %3, %4};"
                 :: "l"(p), "f"(v.x), "f"(v.y), "f"(v.z), "f"(v.w));
}

// ===========================================================================
// Edge passes: 2 lanes per edge (confirmed at the L1tex line floor).
// Lane pair (2k, 2k+1) owns one edge; parity p = lane&1 selects which 16B
// half of the node's 32B batch-chunk this lane handles. One LDG.128 gathers
// (adjacent lanes -> same 32B chunk -> 1 line/edge); one full-warp red.v4
// scatters. Each warp covers 64 contiguous edges; loads batched first.
//
// PDL chain:  prep --(entry trig)--> pass1 --(entry trig)--> pass2
//             pass2 --(POST-sync trig)--> final
// pass1 overlaps its idx/weight prologue with prep. pass2's trigger fires
// only after its sync, so final's blocks launch with pass1 (and prep)
// provably complete -> final preloads fx/err/x BEFORE its own sync and
// only the aggr load waits on pass2.
// ===========================================================================

// pass1: err[tgt] -= w * fx[src]; writes payload {w, (src<<14)|tgt}.
__global__ __launch_bounds__(TBP) void pass1_kernel(
        const void* __restrict__ ei, const float* __restrict__ w) {
    cudaTriggerProgrammaticLaunchCompletion();
    int lane = threadIdx.x & 31;
    int p    = lane & 1;        // 16B half selector
    int eo   = lane >> 1;       // edge slot within warp-step (0..15)
    int warp = blockIdx.x * (TBP / 32) + (threadIdx.x >> 5);
    int base = warp * 64 + eo;

    // self-sniff idx dtype (independent of prep): indices < 10000, so int64
    // means odd 32-bit words are all 0. P(false positive for int32) ~ 1e-16.
    const unsigned int* eiw = (const unsigned int*)ei;
    int idx64 = (eiw[1] == 0u) & (eiw[3] == 0u) & (eiw[5] == 0u) & (eiw[7] == 0u);

    int   s[4], t[4];
    float we[4];
    float4 v[4];

    #pragma unroll
    for (int k = 0; k < 4; k++) {
        int e = base + k * 16;
        if (idx64) {
            s[k] = (int)__ldg((const long long*)ei + e);
            t[k] = (int)__ldg((const long long*)ei + NE + e);
        } else {
            s[k] = __ldg((const int*)ei + e);
            t[k] = __ldg((const int*)ei + NE + e);
        }
        we[k] = __ldg(w + e);
    }
    #pragma unroll
    for (int k = 0; k < 4; k++) {
        int e = base + k * 16;
        if (p == 0)
            g_epay[e] = make_uint2(__float_as_uint(we[k]),
                                   ((unsigned)s[k] << 14) | (unsigned)t[k]);
    }

    cudaGridDependencySynchronize();   // wait for prep's fx/err tables

    #pragma unroll
    for (int k = 0; k < 4; k++) {
        v[k] = __ldg(reinterpret_cast<const float4*>(g_fx) + s[k] * 2 + p);
    }
    #pragma unroll
    for (int k = 0; k < 4; k++) {
        float wk = -we[k];             // negated: err accumulates x - pred
        red_add_v4(g_err + (size_t)t[k] * 8 + p * 4,
                   make_float4(wk * v[k].x, wk * v[k].y,
                               wk * v[k].z, wk * v[k].w));
    }
}

// ---------------------------------------------------------------------------
// pass2: aggr[src] += w * err[tgt].  Trigger AFTER sync: final's blocks then
// launch only once pass1 (hence prep) is fully complete.
__global__ __launch_bounds__(TBP) void pass2_kernel() {
    cudaGridDependencySynchronize();   // wait for pass1 (payload + err)
    cudaTriggerProgrammaticLaunchCompletion();
    int lane = threadIdx.x & 31;
    int p    = lane & 1;
    int eo   = lane >> 1;
    int warp = blockIdx.x * (TBP / 32) + (threadIdx.x >> 5);
    int base = warp * 64 + eo;

    int   s[4], t[4];
    float we[4];
    float4 v[4];

    #pragma unroll
    for (int k = 0; k < 4; k++) {
        uint2 pay = __ldg(g_epay + base + k * 16);
        we[k] = __uint_as_float(pay.x);
        s[k]  = (int)(pay.y >> 14);
        t[k]  = (int)(pay.y & 16383u);
    }
    #pragma unroll
    for (int k = 0; k < 4; k++) {
        v[k] = __ldg(reinterpret_cast<const float4*>(g_err) + t[k] * 2 + p);
    }
    #pragma unroll
    for (int k = 0; k < 4; k++) {
        float wk = we[k];
        red_add_v4(g_aggr + (size_t)s[k] * 8 + p * 4,
                   make_float4(wk * v[k].x, wk * v[k].y,
                               wk * v[k].z, wk * v[k].w));
    }
}

// ---------------------------------------------------------------------------
// final: one thread per (node, batch) element. x reloaded from values (input,
// no ordering needed); fx/err preloaded BEFORE sync (pass1 complete by PDL
// chain); only aggr waits on pass2. pred reconstructed as x - err.
// out layout: [3, B*N], inner [B, N].
__global__ __launch_bounds__(256) void final_kernel(
        const float* __restrict__ values, float* __restrict__ out) {
    int i = blockIdx.x * blockDim.x + threadIdx.x;
    bool ok = (i < NB);
    int ic = ok ? i : 0;
    int n = ic >> 3;
    int b = ic & 7;
    float x  = __ldg(values + b * NV + n);
    float fx = g_fx[ic];
    float er = g_err[ic];

    cudaGridDependencySynchronize();   // wait for pass2 (aggr only)

    if (!ok) return;
    float ag = g_aggr[i];
    float pred = x - er;
    float dx   = er - (1.0f - fx * fx) * ag;
    int o = b * NV + n;
    out[o]          = pred;
    out[NB + o]     = er;
    out[2 * NB + o] = dx;
}

// ---------------------------------------------------------------------------
extern "C" void kernel_launch(void* const* d_in, const int* in_sizes, int n_in,
                              void* d_out, int out_size) {
    const float* values  = (const float*)d_in[0];
    const float* weights = (const float*)d_in[1];
    const void*  ei      = (const void*)d_in[2];
    float* out = (float*)d_out;

    prep_kernel<<<(NB + 255) / 256, 256>>>(values);

    cudaLaunchAttribute attr;
    attr.id = cudaLaunchAttributeProgrammaticStreamSerialization;
    attr.val.programmaticStreamSerializationAllowed = 1;

    cudaLaunchConfig_t cfg = {};
    cfg.attrs = &attr;
    cfg.numAttrs = 1;
    cfg.stream = 0;

    cfg.gridDim = dim3(NBLK);
    cfg.blockDim = dim3(TBP);
    cudaLaunchKernelEx(&cfg, pass1_kernel, (const void*)ei, weights);
    cudaLaunchKernelEx(&cfg, pass2_kernel);

    cfg.gridDim = dim3((NB + 255) / 256);
    cfg.blockDim = dim3(256);
    cudaLaunchKernelEx(&cfg, final_kernel, values, out);
}

// round 14
// speedup vs baseline: 1.2928x; 1.0400x over previous
#include <cuda_runtime.h>
#include <cuda_bf16.h>

#define NV 10000
#define BB 8
#define NE 2000000
#define NB (NV * BB)

// Edge-pass geometry: 64 edges per warp, 31250 warps exactly -> no bounds checks.
#define TBP 320                       // threads per pass CTA (10 warps)
#define NBLK (NE / 64 / (TBP / 32))   // 3125 CTAs

#define NODE_BLOCKS ((NV + 31) / 32)  // 313: each block = 32 nodes x 8 batches

// Node tables in [N, B] layout: each node's 8 batch values = one 32B chunk.
__device__ float g_fx[NB];        // tanh(x)
__device__ float g_err[NB];       // init x; pass1 reds -w*fx -> becomes x-pred
__device__ float g_aggr[NB];      // scatter accumulator (by src)
__device__ uint2 g_epay[NE];      // {w_bits, (src<<14)|tgt} written by pass1

// ---------------------------------------------------------------------------
// prep: block = 32 nodes x 8 batches. Coalesced values reads in (b,n) order,
// smem transpose, coalesced linear table writes in i = n*8+b order.
__global__ __launch_bounds__(256) void prep_kernel(
        const float* __restrict__ values) {
    cudaTriggerProgrammaticLaunchCompletion();
    __shared__ float sx[32][9];            // padded: conflict-free transpose
    int tid = threadIdx.x;
    int n0  = blockIdx.x * 32;

    int r = tid & 31, b = tid >> 5;        // read order: (b, n0+r)
    int n = n0 + r;
    float x = (n < NV) ? __ldg(values + b * NV + n) : 0.0f;
    sx[r][b] = x;
    __syncthreads();

    int rr = tid >> 3, bb = tid & 7;       // write order: i = (n0+rr)*8 + bb
    if (n0 + rr < NV) {
        int i = n0 * 8 + tid;
        float xt = sx[rr][bb];
        g_fx[i]   = tanhf(xt);
        g_err[i]  = xt;      // err starts at x; pass1 subtracts pred via red
        g_aggr[i] = 0.0f;
    }
}

// ---------------------------------------------------------------------------
__device__ __forceinline__ void red_add_v4(float* p, float4 v) {
    asm volatile("red.global.add.v4.f32 [%0], {%1, %2, %3, %4};"
                 :: "l"(p), "f"(v.x), "f"(v.y), "f"(v.z), "f"(v.w));
}

// ===========================================================================
// Edge passes: 2 lanes per edge (confirmed at the L1tex line floor).
// Lane pair (2k, 2k+1) owns one edge; parity p = lane&1 selects which 16B
// half of the node's 32B batch-chunk this lane handles. One LDG.128 gathers
// (adjacent lanes -> same 32B chunk -> 1 line/edge); one full-warp red.v4
// scatters. Each warp covers 64 contiguous edges; loads batched first.
//
// PDL chain:  prep --(entry trig)--> pass1 --(entry trig)--> pass2
//             pass2 --(POST-sync trig)--> final
// ===========================================================================

// pass1: err[tgt] -= w * fx[src]; writes payload {w, (src<<14)|tgt}.
__global__ __launch_bounds__(TBP) void pass1_kernel(
        const void* __restrict__ ei, const float* __restrict__ w) {
    cudaTriggerProgrammaticLaunchCompletion();
    int lane = threadIdx.x & 31;
    int p    = lane & 1;        // 16B half selector
    int eo   = lane >> 1;       // edge slot within warp-step (0..15)
    int warp = blockIdx.x * (TBP / 32) + (threadIdx.x >> 5);
    int base = warp * 64 + eo;

    // self-sniff idx dtype (independent of prep): indices < 10000, so int64
    // means odd 32-bit words are all 0. P(false positive for int32) ~ 1e-16.
    const unsigned int* eiw = (const unsigned int*)ei;
    int idx64 = (eiw[1] == 0u) & (eiw[3] == 0u) & (eiw[5] == 0u) & (eiw[7] == 0u);

    int   s[4], t[4];
    float we[4];
    float4 v[4];

    #pragma unroll
    for (int k = 0; k < 4; k++) {
        int e = base + k * 16;
        if (idx64) {
            s[k] = (int)__ldg((const long long*)ei + e);
            t[k] = (int)__ldg((const long long*)ei + NE + e);
        } else {
            s[k] = __ldg((const int*)ei + e);
            t[k] = __ldg((const int*)ei + NE + e);
        }
        we[k] = __ldg(w + e);
    }
    #pragma unroll
    for (int k = 0; k < 4; k++) {
        int e = base + k * 16;
        if (p == 0)
            g_epay[e] = make_uint2(__float_as_uint(we[k]),
                                   ((unsigned)s[k] << 14) | (unsigned)t[k]);
    }

    cudaGridDependencySynchronize();   // wait for prep's fx/err tables

    #pragma unroll
    for (int k = 0; k < 4; k++) {
        v[k] = __ldg(reinterpret_cast<const float4*>(g_fx) + s[k] * 2 + p);
    }
    #pragma unroll
    for (int k = 0; k < 4; k++) {
        float wk = -we[k];             // negated: err accumulates x - pred
        red_add_v4(g_err + (size_t)t[k] * 8 + p * 4,
                   make_float4(wk * v[k].x, wk * v[k].y,
                               wk * v[k].z, wk * v[k].w));
    }
}

// ---------------------------------------------------------------------------
// pass2: aggr[src] += w * err[tgt].  Trigger AFTER sync: final's blocks then
// launch only once pass1 (hence prep) is fully complete.
__global__ __launch_bounds__(TBP) void pass2_kernel() {
    cudaGridDependencySynchronize();   // wait for pass1 (payload + err)
    cudaTriggerProgrammaticLaunchCompletion();
    int lane = threadIdx.x & 31;
    int p    = lane & 1;
    int eo   = lane >> 1;
    int warp = blockIdx.x * (TBP / 32) + (threadIdx.x >> 5);
    int base = warp * 64 + eo;

    int   s[4], t[4];
    float we[4];
    float4 v[4];

    #pragma unroll
    for (int k = 0; k < 4; k++) {
        uint2 pay = __ldg(g_epay + base + k * 16);
        we[k] = __uint_as_float(pay.x);
        s[k]  = (int)(pay.y >> 14);
        t[k]  = (int)(pay.y & 16383u);
    }
    #pragma unroll
    for (int k = 0; k < 4; k++) {
        v[k] = __ldg(reinterpret_cast<const float4*>(g_err) + t[k] * 2 + p);
    }
    #pragma unroll
    for (int k = 0; k < 4; k++) {
        float wk = we[k];
        red_add_v4(g_aggr + (size_t)s[k] * 8 + p * 4,
                   make_float4(wk * v[k].x, wk * v[k].y,
                               wk * v[k].z, wk * v[k].w));
    }
}

// ---------------------------------------------------------------------------
// final: block = 32 nodes x 8 batches.
// Phase A (pre-sync: pass1 complete by PDL chain): coalesced i-order reads of
// fx/err; prefetch x in output order. Post-sync: coalesced aggr read, dx,
// smem transpose. Phase B: fully coalesced writes of all 3 output streams at
// o = b*NV + n; pred = x - err computed here.
// out layout: [3, B*N], inner [B, N].
__global__ __launch_bounds__(256) void final_kernel(
        const float* __restrict__ values, float* __restrict__ out) {
    __shared__ float ser[32][9];
    __shared__ float sdx[32][9];
    int tid = threadIdx.x;
    int n0  = blockIdx.x * 32;

    int rr = tid >> 3, bb = tid & 7;       // table order: i = (n0+rr)*8 + bb
    int i  = n0 * 8 + tid;
    bool okA = (n0 + rr < NV);
    int ic = okA ? i : 0;
    float fx = g_fx[ic];
    float er = g_err[ic];

    int rB = tid & 31, bB = tid >> 5;      // output order: o = bB*NV + n0+rB
    int nB = n0 + rB;
    bool okB = (nB < NV);
    int o = bB * NV + (okB ? nB : 0);
    float x = __ldg(values + o);           // input: no ordering needed

    cudaGridDependencySynchronize();       // wait for pass2 (aggr only)

    if (okA) {
        float ag = g_aggr[i];
        ser[rr][bb] = er;
        sdx[rr][bb] = er - (1.0f - fx * fx) * ag;
    }
    __syncthreads();

    if (okB) {
        float er_t = ser[rB][bB];
        out[o]          = x - er_t;        // pred
        out[NB + o]     = er_t;            // err
        out[2 * NB + o] = sdx[rB][bB];     // dx
    }
}

// ---------------------------------------------------------------------------
extern "C" void kernel_launch(void* const* d_in, const int* in_sizes, int n_in,
                              void* d_out, int out_size) {
    const float* values  = (const float*)d_in[0];
    const float* weights = (const float*)d_in[1];
    const void*  ei      = (const void*)d_in[2];
    float* out = (float*)d_out;

    prep_kernel<<<NODE_BLOCKS, 256>>>(values);

    cudaLaunchAttribute attr;
    attr.id = cudaLaunchAttributeProgrammaticStreamSerialization;
    attr.val.programmaticStreamSerializationAllowed = 1;

    cudaLaunchConfig_t cfg = {};
    cfg.attrs = &attr;
    cfg.numAttrs = 1;
    cfg.stream = 0;

    cfg.gridDim = dim3(NBLK);
    cfg.blockDim = dim3(TBP);
    cudaLaunchKernelEx(&cfg, pass1_kernel, (const void*)ei, weights);
    cudaLaunchKernelEx(&cfg, pass2_kernel);

    cfg.gridDim = dim3(NODE_BLOCKS);
    cfg.blockDim = dim3(256);
    cudaLaunchKernelEx(&cfg, final_kernel, values, out);
}